// round 16
// baseline (speedup 1.0000x reference)
#include <cuda_runtime.h>
#include <cuda_bf16.h>
#include <math.h>

#define BB 4
#define SS 4096
#define DD 1024
#define HALF (DD/2)
#define TD (3*DD)
#define QKD (2*DD)

// ---------------- scratch (device globals; no allocation allowed) ----------------
__device__ __align__(16) __nv_bfloat16  g_qkbf[(long long)BB*SS*QKD];   // 64MB q,k rows
__device__ __align__(16) __nv_bfloat16  g_P[(long long)BB*SS*SS];       // 128MB unnormalized 3^s
__device__ __align__(16) __nv_bfloat16  g_hbf[(long long)BB*SS*DD];     // 32MB
__device__ __align__(16) unsigned char  g_qf8[(long long)BB*SS*DD];     // 16MB e4m3
__device__ __align__(16) unsigned char  g_kf8[(long long)BB*SS*DD];     // 16MB e4m3
__device__ __align__(16) __nv_bfloat16  g_vwT[(long long)DD*BB*SS];     // 32MB (h@Wvp)^T [d][b*s]
__device__ __align__(16) __nv_bfloat16  g_wqkT[(long long)QKD*DD];      // 4MB  [n][k]
__device__ __align__(16) __nv_bfloat16  g_wprojT[(long long)DD*DD];     // 2MB  [n][k]
__device__ __align__(16) __nv_bfloat16  g_wvbf[(long long)DD*DD];       // 2MB  Wv rows bf16 [in][mid]
__device__ __align__(16) __nv_bfloat16  g_wvpT[(long long)DD*DD];       // 2MB  (Wv@Wproj)^T [out][in]
__device__ float g_bfin[DD];                                            // b_proj + bv@Wproj
__device__ float g_den[(long long)BB*SS];                               // row sums of P
__device__ float g_invf[HALF];
__device__ __align__(8) signed char g_cos[SS*HALF];
__device__ __align__(8) signed char g_sin[SS*HALF];

// ---------------- fast exp2 (always single MUFU regardless of fast-math flags) ----------------
__device__ __forceinline__ float ex2f(float x) {
    float r;
    asm("ex2.approx.ftz.f32 %0, %1;" : "=f"(r) : "f"(x));
    return r;
}

// ---------------- ternary rope tables ----------------
__global__ void build_inv_kernel() {
    int j = threadIdx.x;
    float e = (float)j / (float)HALF;
    g_invf[j] = 1.0f / (float)pow(10000.0, (double)e);
}
__global__ void build_tables_kernel() {
    int idx = blockIdx.x * blockDim.x + threadIdx.x;
    if (idx >= SS * HALF) return;
    int s = idx / HALF;
    int j = idx - s * HALF;
    float ang = (float)s * g_invf[j];
    double t = (double)ang;
    double k = rint(t * 0.15915494309189535);
    float r = (float)(t - k * 6.283185307179586);
    float c, sn;
    sincosf(r, &sn, &c);
    g_cos[idx] = (signed char)__float2int_rn(c);
    g_sin[idx] = (signed char)__float2int_rn(sn);
}

// ---------------- out = x copy (stream B; out is RED-accumulated by final GEMM) ----------------
__global__ __launch_bounds__(256) void copy_x_kernel(const uint4* __restrict__ x, uint4* __restrict__ out) {
    long long i = (long long)blockIdx.x * 256 + threadIdx.x;   // 4M uint4 = 64MB
    out[i] = x[i];
}

// ---------------- zero vwT + wvpT (split-K RED accumulators), on stream B ----------------
#define NZ1 ((long long)DD*BB*SS/8)   // vwT in uint4
#define NZ2 ((long long)DD*DD/8)      // wvpT in uint4
__global__ void prep_zero_kernel(uint4* __restrict__ vw, uint4* __restrict__ wvp) {
    long long i = (long long)blockIdx.x * 256 + threadIdx.x;
    if (i < NZ1) vw[i] = make_uint4(0u, 0u, 0u, 0u);
    else if (i < NZ1 + NZ2) wvp[i - NZ1] = make_uint4(0u, 0u, 0u, 0u);
}

// ---------------- bfinal[j] = b_proj[j] + sum_l b_qkv[2048+l] * w_proj[l][j]  (stream B) ----------------
__global__ void bfin_kernel(const float* __restrict__ b_qkv, const float* __restrict__ w_proj,
                            const float* __restrict__ b_proj) {
    int j = blockIdx.x * 256 + threadIdx.x;
    float acc = b_proj[j];
    for (int l = 0; l < DD; l++) acc += b_qkv[2 * DD + l] * w_proj[(long long)l * DD + j];
    g_bfin[j] = acc;
}

// ---------------- convert Wv slice to bf16 (no transpose): wv[in][mid] ----------------
__global__ __launch_bounds__(256) void cvt_wv_kernel(const float* __restrict__ w_qkv,
                                                     __nv_bfloat16* __restrict__ wv) {
    int idx = blockIdx.x * 256 + threadIdx.x;
    int row = idx >> 8, col4 = (idx & 255) * 4;
    float4 v = *(const float4*)(w_qkv + (long long)row * TD + 2 * DD + col4);
    __nv_bfloat162 o0 = {__float2bfloat16(v.x), __float2bfloat16(v.y)};
    __nv_bfloat162 o1 = {__float2bfloat16(v.z), __float2bfloat16(v.w)};
    __nv_bfloat162* op = (__nv_bfloat162*)(wv + (long long)row * DD + col4);
    op[0] = o0; op[1] = o1;
}

// ---------------- reductions ----------------
__device__ __forceinline__ float block_reduce_sum(float v, float* red) {
    int lane = threadIdx.x & 31, w = threadIdx.x >> 5;
    #pragma unroll
    for (int o = 16; o; o >>= 1) v += __shfl_xor_sync(0xffffffffu, v, o);
    if (lane == 0) red[w] = v;
    __syncthreads();
    if (w == 0) {
        v = (lane < (int)(blockDim.x >> 5)) ? red[lane] : 0.0f;
        #pragma unroll
        for (int o = 16; o; o >>= 1) v += __shfl_xor_sync(0xffffffffu, v, o);
        if (lane == 0) red[0] = v;
    }
    __syncthreads();
    float out = red[0];
    __syncthreads();
    return out;
}

// ---------------- rmsnorm -> bf16 (lean: x read + h write only) ----------------
__global__ __launch_bounds__(256) void rmsnorm_kernel(const float* __restrict__ x,
                                                      const float* __restrict__ g,
                                                      __nv_bfloat16* __restrict__ h) {
    __shared__ float red[32];
    long long base = (long long)blockIdx.x * DD;
    float4 v = *(const float4*)(x + base + (long long)threadIdx.x * 4);
    float ss = v.x*v.x + v.y*v.y + v.z*v.z + v.w*v.w;
    float total = block_reduce_sum(ss, red);
    float r = rsqrtf(total * (1.0f / DD) + 1e-6f);
    float4 gv = *(const float4*)(g + (long long)threadIdx.x * 4);
    __nv_bfloat162 h0 = {__float2bfloat16(v.x*r*gv.x), __float2bfloat16(v.y*r*gv.y)};
    __nv_bfloat162 h1 = {__float2bfloat16(v.z*r*gv.z), __float2bfloat16(v.w*r*gv.w)};
    __nv_bfloat162* hp = (__nv_bfloat162*)(h + base + (long long)threadIdx.x * 4);
    hp[0] = h0; hp[1] = h1;
}

// ---------------- weight transpose + convert f32 -> bf16 ----------------
__global__ __launch_bounds__(256) void transpose_cvt_kernel(
    const float* __restrict__ in, int ldin,
    __nv_bfloat16* __restrict__ out, int ldout)
{
    __shared__ float tile[32][33];
    int r0 = blockIdx.y * 32, c0 = blockIdx.x * 32;
    int tx = threadIdx.x & 31, ty = threadIdx.x >> 5;
    #pragma unroll
    for (int i = 0; i < 4; i++)
        tile[ty + i * 8][tx] = in[(long long)(r0 + ty + i * 8) * ldin + c0 + tx];
    __syncthreads();
    #pragma unroll
    for (int i = 0; i < 4; i++)
        out[(long long)(c0 + ty + i * 8) * ldout + r0 + tx] = __float2bfloat16(tile[tx][ty + i * 8]);
}

// ---------------- rope (vectorized): bf16 qk -> e4m3 q,k ; zeroes den ----------------
__device__ __forceinline__ unsigned short cvt_e4m3x2(float lo, float hi) {
    unsigned short r;
    asm("cvt.rn.satfinite.e4m3x2.f32 %0, %1, %2;" : "=h"(r) : "f"(hi), "f"(lo));
    return r;
}
__global__ __launch_bounds__(256) void rope_kernel(const __nv_bfloat16* __restrict__ qk,
                                                   unsigned char* __restrict__ qo,
                                                   unsigned char* __restrict__ ko,
                                                   float* __restrict__ den) {
    int r = blockIdx.x * 4 + (threadIdx.x >> 6);
    if (threadIdx.x < 4) den[blockIdx.x * 4 + threadIdx.x] = 0.0f;
    int s = r & (SS - 1);
    int j = (threadIdx.x & 63) * 8;

    long long tc8 = *(const long long*)&g_cos[s * HALF + j];
    long long ts8 = *(const long long*)&g_sin[s * HALF + j];
    float cs[8], sn[8];
    #pragma unroll
    for (int i = 0; i < 8; i++) {
        cs[i] = (float)(signed char)(tc8 >> (8 * i));
        sn[i] = (float)(signed char)(ts8 >> (8 * i));
    }

    long long rb = (long long)r * QKD;
    long long ob = (long long)r * DD;
    #pragma unroll
    for (int w = 0; w < 2; w++) {
        const __nv_bfloat16* src = qk + rb + (w ? DD : 0);
        unsigned char* dst = w ? ko : qo;
        uint4 ua = *(const uint4*)(src + j);
        uint4 ub = *(const uint4*)(src + j + HALF);
        float a[8], b[8];
        unsigned va[4] = {ua.x, ua.y, ua.z, ua.w};
        unsigned vb[4] = {ub.x, ub.y, ub.z, ub.w};
        #pragma unroll
        for (int p = 0; p < 4; p++) {
            float2 fa = __bfloat1622float2(*(__nv_bfloat162*)&va[p]);
            float2 fb = __bfloat1622float2(*(__nv_bfloat162*)&vb[p]);
            a[2*p] = fa.x; a[2*p+1] = fa.y;
            b[2*p] = fb.x; b[2*p+1] = fb.y;
        }
        unsigned short lo[4], hi[4];
        #pragma unroll
        for (int p = 0; p < 4; p++) {
            lo[p] = cvt_e4m3x2(a[2*p]*cs[2*p]   - b[2*p]*sn[2*p],
                               a[2*p+1]*cs[2*p+1] - b[2*p+1]*sn[2*p+1]);
            hi[p] = cvt_e4m3x2(b[2*p]*cs[2*p]   + a[2*p]*sn[2*p],
                               b[2*p+1]*cs[2*p+1] + a[2*p+1]*sn[2*p+1]);
        }
        *(uint2*)(dst + ob + j)        = make_uint2((unsigned)lo[0] | ((unsigned)lo[1] << 16),
                                                    (unsigned)lo[2] | ((unsigned)lo[3] << 16));
        *(uint2*)(dst + ob + HALF + j) = make_uint2((unsigned)hi[0] | ((unsigned)hi[1] << 16),
                                                    (unsigned)hi[2] | ((unsigned)hi[3] << 16));
    }
}

// ---------------- mma helpers ----------------
__device__ __forceinline__ void ldsm4(unsigned* r, unsigned addr) {
    asm volatile("ldmatrix.sync.aligned.m8n8.x4.shared.b16 {%0,%1,%2,%3},[%4];"
                 : "=r"(r[0]), "=r"(r[1]), "=r"(r[2]), "=r"(r[3]) : "r"(addr));
}
__device__ __forceinline__ void mma_bf16(float* c, const unsigned* a, unsigned b0, unsigned b1) {
    asm volatile("mma.sync.aligned.m16n8k16.row.col.f32.bf16.bf16.f32 "
                 "{%0,%1,%2,%3},{%4,%5,%6,%7},{%8,%9},{%0,%1,%2,%3};"
                 : "+f"(c[0]), "+f"(c[1]), "+f"(c[2]), "+f"(c[3])
                 : "r"(a[0]), "r"(a[1]), "r"(a[2]), "r"(a[3]), "r"(b0), "r"(b1));
}
__device__ __forceinline__ void mma_e4m3(float* c, const unsigned* a, unsigned b0, unsigned b1) {
    asm volatile("mma.sync.aligned.m16n8k32.row.col.f32.e4m3.e4m3.f32 "
                 "{%0,%1,%2,%3},{%4,%5,%6,%7},{%8,%9},{%0,%1,%2,%3};"
                 : "+f"(c[0]), "+f"(c[1]), "+f"(c[2]), "+f"(c[3])
                 : "r"(a[0]), "r"(a[1]), "r"(a[2]), "r"(a[3]), "r"(b0), "r"(b1));
}
__device__ __forceinline__ void cpasync16(unsigned s, const void* g) {
    asm volatile("cp.async.cg.shared.global [%0], [%1], 16;" :: "r"(s), "l"(g));
}
#define CP_COMMIT() asm volatile("cp.async.commit_group;" ::: "memory")

__device__ __forceinline__ void red_add_f2(float* addr, float a, float b) {
    asm volatile("red.global.add.v2.f32 [%0], {%1, %2};" :: "l"(addr), "f"(a), "f"(b) : "memory");
}
__device__ __forceinline__ void red_add_bf2(__nv_bfloat16* addr, float a, float b) {
    __nv_bfloat162 pv = __floats2bfloat162_rn(a, b);
    unsigned u = *(unsigned*)&pv;
    asm volatile("red.global.add.noftz.bf16x2 [%0], %1;" :: "l"(addr), "r"(u) : "memory");
}

__device__ __forceinline__ unsigned swz(int row, int ch) {
    int o = row * 128 + ch * 16;
    return (unsigned)(o ^ ((o >> 3) & 0x70));
}

// ================= persistent TN GEMM: tile 128x256, 128B k-chunks =================
// EPI: 1 = bf16 out (+bias), 2 = bf16 out = 3^(acc*alpha) + row-sum atomics into dptr,
//      3 = bf16 out plain (SPLITK: RED bf16x2 into pre-zeroed out),
//      4 = RED f32: out += acc/dptr[row] + (hk==0 ? bias : 0)  (out pre-initialized to x)
#define STG 49152u
template <int IN8, int EPI, int SPLITK>
__global__ __launch_bounds__(256) void gemm_tc(
    int T, int gx, int gy, int gz,
    const char* __restrict__ A0, long long ldaB, long long sAB,
    const char* __restrict__ B0, long long ldbB, long long sBB,
    void* __restrict__ Cv, int ldc, long long sC,
    float alpha,
    const float* __restrict__ bias,
    float* __restrict__ dptr, long long sRS)
{
    extern __shared__ __align__(1024) char dsm[];
    unsigned sbase = (unsigned)__cvta_generic_to_shared(dsm);

    const int t = threadIdx.x;
    const int G = gridDim.x;
    const int gxy = gx * gy;
    const int ntL = gxy * gz;
    const int ntP = SPLITK ? ntL * 2 : ntL;
    const int myCount = (ntP - (int)blockIdx.x + G - 1) / G;
    if (myCount <= 0) return;
    const int myTotal = myCount * T;

    const int lrow = t >> 3;
    const int lch  = t & 7;
    const int warp = t >> 5;
    const int wm = warp >> 2;
    const int wn = warp & 3;
    const int lane = t & 31;
    const int lrow16 = lane & 15;
    const int lhalf  = lane >> 4;

    float acc[4][8][4];
    #pragma unroll
    for (int i = 0; i < 4; i++)
        #pragma unroll
        for (int j = 0; j < 8; j++)
            #pragma unroll
            for (int v = 0; v < 4; v++) acc[i][j][v] = 0.0f;

    auto prefetchChunk = [&](int j) {
        if (j < myTotal) {
            int i = j / T, c = j - i * T;
            int p = (int)blockIdx.x + i * G;
            int lt = SPLITK ? (p >> 1) : p;
            int hk = SPLITK ? (p & 1) : 0;
            int z2 = lt / gxy; int rr = lt - z2 * gxy;
            int by = rr / gx, bx = rr - by * gx;
            const char* Ap = A0 + z2 * sAB + (long long)(by * 128) * ldaB;
            const char* Bp = B0 + z2 * sBB + (long long)(bx * 256) * ldbB;
            unsigned aB = sbase + (unsigned)(j % 3) * STG;
            unsigned bB = aB + 16384u;
            long long ko = (long long)c * 128 + lch * 16 + (long long)hk * T * 128;
            #pragma unroll
            for (int ii = 0; ii < 4; ii++)
                cpasync16(aB + swz(lrow + ii * 32, lch), Ap + (long long)(lrow + ii * 32) * ldaB + ko);
            #pragma unroll
            for (int ii = 0; ii < 8; ii++)
                cpasync16(bB + swz(lrow + ii * 32, lch), Bp + (long long)(lrow + ii * 32) * ldbB + ko);
        }
        CP_COMMIT();
    };

    prefetchChunk(0);
    prefetchChunk(1);

    for (int i = 0; i < myCount; i++) {
        for (int c = 0; c < T; c++) {
            int j = i * T + c;
            if (j + 1 < myTotal) {
                asm volatile("cp.async.wait_group 1;" ::: "memory");
            } else {
                asm volatile("cp.async.wait_group 0;" ::: "memory");
            }
            __syncthreads();

            prefetchChunk(j + 2);

            unsigned aB = sbase + (unsigned)(j % 3) * STG;
            unsigned bB = aB + 16384u;

            unsigned afrag[2][4][4], bfrag[2][4][4];
            #pragma unroll
            for (int mi = 0; mi < 4; mi++)
                ldsm4(afrag[0][mi], aB + swz(wm * 64 + mi * 16 + lrow16, lhalf));
            #pragma unroll
            for (int p = 0; p < 4; p++)
                ldsm4(bfrag[0][p], bB + swz(wn * 64 + p * 16 + lrow16, lhalf));

            #pragma unroll
            for (int ks = 0; ks < 4; ks++) {
                int cur = ks & 1, nxt = cur ^ 1;
                if (ks < 3) {
                    #pragma unroll
                    for (int mi = 0; mi < 4; mi++)
                        ldsm4(afrag[nxt][mi], aB + swz(wm * 64 + mi * 16 + lrow16, (ks + 1) * 2 + lhalf));
                    #pragma unroll
                    for (int p = 0; p < 4; p++)
                        ldsm4(bfrag[nxt][p], bB + swz(wn * 64 + p * 16 + lrow16, (ks + 1) * 2 + lhalf));
                }
                #pragma unroll
                for (int mi = 0; mi < 4; mi++) {
                    #pragma unroll
                    for (int ni = 0; ni < 8; ni++) {
                        const unsigned* bf = bfrag[cur][ni >> 1];
                        if (IN8) mma_e4m3(acc[mi][ni], afrag[cur][mi], bf[ni & 1], bf[2 + (ni & 1)]);
                        else     mma_bf16(acc[mi][ni], afrag[cur][mi], bf[ni & 1], bf[2 + (ni & 1)]);
                    }
                }
            }
        }

        // ---------------- epilogue ----------------
        {
            int p = (int)blockIdx.x + i * G;
            int lt = SPLITK ? (p >> 1) : p;
            int hk = SPLITK ? (p & 1) : 0;
            int z = lt / gxy; int rr = lt - z * gxy;
            int by = rr / gx, bx = rr - by * gx;
            int m0 = by * 128, n0 = bx * 256;
            const int g = lane >> 2, tig = lane & 3;
            #pragma unroll
            for (int mi = 0; mi < 4; mi++) {
                #pragma unroll
                for (int half = 0; half < 2; half++) {
                    int row = m0 + wm * 64 + mi * 16 + g + half * 8;
                    float rs = 0.0f;
                    if (EPI == 4) rs = 1.0f / dptr[z * sRS + row];
                    float rsum = 0.0f;
                    #pragma unroll
                    for (int ni = 0; ni < 8; ni++) {
                        int col = n0 + wn * 64 + ni * 8 + tig * 2;
                        float v0 = acc[mi][ni][half * 2];
                        float v1 = acc[mi][ni][half * 2 + 1];
                        if (EPI == 1) {
                            v0 += bias[col]; v1 += bias[col + 1];
                            __nv_bfloat16* C = (__nv_bfloat16*)Cv + z * sC;
                            __nv_bfloat162 pv = {__float2bfloat16(v0), __float2bfloat16(v1)};
                            *(__nv_bfloat162*)(C + (long long)row * ldc + col) = pv;
                        } else if (EPI == 2) {
                            v0 = ex2f(v0 * alpha); v1 = ex2f(v1 * alpha); rsum += v0 + v1;
                            __nv_bfloat16* C = (__nv_bfloat16*)Cv + z * sC;
                            __nv_bfloat162 pv = {__float2bfloat16(v0), __float2bfloat16(v1)};
                            *(__nv_bfloat162*)(C + (long long)row * ldc + col) = pv;
                        } else if (EPI == 3) {
                            __nv_bfloat16* C = (__nv_bfloat16*)Cv + z * sC;
                            if (SPLITK) {
                                red_add_bf2(C + (long long)row * ldc + col, v0, v1);
                            } else {
                                __nv_bfloat162 pv = {__float2bfloat16(v0), __float2bfloat16(v1)};
                                *(__nv_bfloat162*)(C + (long long)row * ldc + col) = pv;
                            }
                        } else {   // EPI == 4: RED accumulate + one-shot bias on hk==0
                            float b0 = 0.0f, b1 = 0.0f;
                            if (hk == 0) { b0 = bias[col]; b1 = bias[col + 1]; }
                            float* C = (float*)Cv + z * sC;
                            red_add_f2(C + (long long)row * ldc + col, v0 * rs + b0, v1 * rs + b1);
                        }
                    }
                    if (EPI == 2) {
                        rsum += __shfl_xor_sync(0xffffffffu, rsum, 1);
                        rsum += __shfl_xor_sync(0xffffffffu, rsum, 2);
                        if (tig == 0) atomicAdd(dptr + z * sRS + row, rsum);
                    }
                }
            }
        }
        #pragma unroll
        for (int a = 0; a < 4; a++)
            #pragma unroll
            for (int b = 0; b < 8; b++)
                #pragma unroll
                for (int v = 0; v < 4; v++) acc[a][b][v] = 0.0f;
    }
}

// ---------------- launch ----------------
extern "C" void kernel_launch(void* const* d_in, const int* in_sizes, int n_in,
                              void* d_out, int out_size) {
    const float* x      = (const float*)d_in[0];
    const float* g_norm = (const float*)d_in[1];
    const float* w_qkv  = (const float*)d_in[2];
    const float* b_qkv  = (const float*)d_in[3];
    const float* w_proj = (const float*)d_in[4];
    const float* b_proj = (const float*)d_in[5];
    float* out = (float*)d_out;

    void *pqk, *pP, *ph, *pq, *pk, *pvw, *pwq, *pwp, *pwv, *pwvp, *pd, *pbf;
    cudaGetSymbolAddress(&pqk, g_qkbf);
    cudaGetSymbolAddress(&pP, g_P);
    cudaGetSymbolAddress(&ph, g_hbf);
    cudaGetSymbolAddress(&pq, g_qf8);
    cudaGetSymbolAddress(&pk, g_kf8);
    cudaGetSymbolAddress(&pvw, g_vwT);
    cudaGetSymbolAddress(&pwq, g_wqkT);
    cudaGetSymbolAddress(&pwp, g_wprojT);
    cudaGetSymbolAddress(&pwv, g_wvbf);
    cudaGetSymbolAddress(&pwvp, g_wvpT);
    cudaGetSymbolAddress(&pd, g_den);
    cudaGetSymbolAddress(&pbf, g_bfin);
    __nv_bfloat16* qkbf  = (__nv_bfloat16*)pqk;
    __nv_bfloat16* P     = (__nv_bfloat16*)pP;
    __nv_bfloat16* hbf   = (__nv_bfloat16*)ph;
    unsigned char* qf8   = (unsigned char*)pq;
    unsigned char* kf8   = (unsigned char*)pk;
    __nv_bfloat16* vwT   = (__nv_bfloat16*)pvw;
    __nv_bfloat16* wqkT  = (__nv_bfloat16*)pwq;
    __nv_bfloat16* wprojT= (__nv_bfloat16*)pwp;
    __nv_bfloat16* wvbf  = (__nv_bfloat16*)pwv;
    __nv_bfloat16* wvpT  = (__nv_bfloat16*)pwvp;
    float* den           = (float*)pd;
    float* bfin          = (float*)pbf;

    int sm = 148;
    cudaDeviceGetAttribute(&sm, cudaDevAttrMultiProcessorCount, 0);

    const int SMEM = 3 * (int)STG;   // 144KB
    cudaFuncSetAttribute(gemm_tc<0,1,0>, cudaFuncAttributeMaxDynamicSharedMemorySize, SMEM);
    cudaFuncSetAttribute(gemm_tc<0,3,1>, cudaFuncAttributeMaxDynamicSharedMemorySize, SMEM);
    cudaFuncSetAttribute(gemm_tc<1,2,0>, cudaFuncAttributeMaxDynamicSharedMemorySize, SMEM);
    cudaFuncSetAttribute(gemm_tc<0,4,1>, cudaFuncAttributeMaxDynamicSharedMemorySize, SMEM);

    // one-time stream/event creation (first call is the uncaptured correctness run)
    static cudaStream_t sB = nullptr;
    static cudaEvent_t evFork, evWqk, evTab, evH, evVW;
    if (!sB) {
        cudaStreamCreateWithFlags(&sB, cudaStreamNonBlocking);
        cudaEventCreateWithFlags(&evFork, cudaEventDisableTiming);
        cudaEventCreateWithFlags(&evWqk, cudaEventDisableTiming);
        cudaEventCreateWithFlags(&evTab, cudaEventDisableTiming);
        cudaEventCreateWithFlags(&evH, cudaEventDisableTiming);
        cudaEventCreateWithFlags(&evVW, cudaEventDisableTiming);
    }

    // ---- fork stream B off the main (capturing) stream ----
    cudaEventRecord(evFork, 0);
    cudaStreamWaitEvent(sB, evFork, 0);

    // ---- stream B: wqk transpose (gate for QK GEMM), out=x copy, tables, prep, bfinal, wvp GEMM ----
    transpose_cvt_kernel<<<dim3(QKD / 32, DD / 32), 256, 0, sB>>>(w_qkv, TD, wqkT, DD);
    cudaEventRecord(evWqk, sB);
    copy_x_kernel<<<(int)((long long)BB * SS * DD / 4 / 256), 256, 0, sB>>>((const uint4*)x, (uint4*)out);
    build_inv_kernel<<<1, HALF, 0, sB>>>();
    build_tables_kernel<<<(SS * HALF + 255) / 256, 256, 0, sB>>>();
    cudaEventRecord(evTab, sB);
    cvt_wv_kernel<<<DD * DD / 1024, 256, 0, sB>>>(w_qkv, wvbf);
    transpose_cvt_kernel<<<dim3(DD / 32, DD / 32), 256, 0, sB>>>(w_proj, DD, wprojT, DD);
    prep_zero_kernel<<<(int)((NZ1 + NZ2 + 255) / 256), 256, 0, sB>>>((uint4*)vwT, (uint4*)wvpT);
    bfin_kernel<<<DD / 256, 256, 0, sB>>>(b_qkv, w_proj, b_proj);
    {   // wvpT = (Wv@Wproj)^T  (M=1024,N=1024,K=1024; split-K=2 RED bf16x2)
        int gx = DD / 256, gy = DD / 128, gz = 1;
        int ntP = 2 * gx * gy * gz, G = ntP < sm ? ntP : sm;
        gemm_tc<0,3,1><<<G, 256, SMEM, sB>>>(
            DD * 2 / 128 / 2, gx, gy, gz,
            (const char*)wprojT, DD * 2, 0LL,
            (const char*)wvbf, DD * 2, 0LL,
            wvpT, DD, 0LL,
            1.0f, nullptr, nullptr, 0LL);
    }

    // ---- stream A (main): rmsnorm -> QK GEMM ----
    rmsnorm_kernel<<<BB * SS, 256>>>(x, g_norm, hbf);
    cudaEventRecord(evH, 0);
    cudaStreamWaitEvent(0, evWqk, 0);
    {   // qk = h @ w_qk + b_qk -> bf16  (M=16384, N=2048, K=1024)
        int gx = QKD / 256, gy = (BB * SS) / 128, gz = 1;
        int nt = gx * gy * gz, G = nt < sm ? nt : sm;
        gemm_tc<0,1,0><<<G, 256, SMEM>>>(
            DD * 2 / 128, gx, gy, gz,
            (const char*)hbf, DD * 2, 0LL,
            (const char*)wqkT, DD * 2, 0LL,
            qkbf, QKD, 0LL,
            1.0f, b_qkv, nullptr, 0LL);
    }

    // ---- stream B: vw GEMM once h is ready ----
    cudaStreamWaitEvent(sB, evH, 0);
    {   // vwT[d][b*s] += wvpT @ h^T  (M=1024, N=16384, K=1024; split-K=2 RED bf16x2)
        int gx = (BB * SS) / 256, gy = DD / 128, gz = 1;
        int ntP = 2 * gx * gy * gz, G = ntP < sm ? ntP : sm;
        gemm_tc<0,3,1><<<G, 256, SMEM, sB>>>(
            DD * 2 / 128 / 2, gx, gy, gz,
            (const char*)wvpT, DD * 2, 0LL,
            (const char*)hbf, DD * 2, 0LL,
            vwT, BB * SS, 0LL,
            1.0f, nullptr, nullptr, 0LL);
    }
    cudaEventRecord(evVW, sB);

    // ---- stream A: rope (needs tables) -> P GEMM ----
    cudaStreamWaitEvent(0, evTab, 0);
    rope_kernel<<<BB * SS / 4, 256>>>(qkbf, qf8, kf8, den);
    {   // P = 3^(q@k^T / 32) -> bf16, fused row-sum atomics into den  (M=N=4096, K=1024 fp8)
        int gx = SS / 256, gy = SS / 128, gz = BB;
        int nt = gx * gy * gz, G = nt < sm ? nt : sm;
        gemm_tc<1,2,0><<<G, 256, SMEM>>>(
            DD / 128, gx, gy, gz,
            (const char*)qf8, DD, (long long)SS * DD,
            (const char*)kf8, DD, (long long)SS * DD,
            P, SS, (long long)SS * SS,
            1.5849625007211562f / 32.0f, nullptr, den, (long long)SS);
    }

    // ---- join B, then final GEMM on A ----
    cudaStreamWaitEvent(0, evVW, 0);
    {   // out += (P @ vwT^T)/den + bfinal (hk0 only)   (split-K=2 RED f32; out pre-initialized to x)
        int gx = DD / 256, gy = SS / 128, gz = BB;
        int ntP = 2 * gx * gy * gz, G = ntP < sm ? ntP : sm;
        gemm_tc<0,4,1><<<G, 256, SMEM>>>(
            SS * 2 / 128 / 2, gx, gy, gz,
            (const char*)P, (long long)SS * 2, (long long)SS * SS * 2,
            (const char*)vwT, (long long)BB * SS * 2, (long long)SS * 2,
            out, DD, (long long)SS * DD,
            1.0f, bfin, den, (long long)SS);
    }
}

// round 17
// speedup vs baseline: 1.0648x; 1.0648x over previous
#include <cuda_runtime.h>
#include <cuda_bf16.h>
#include <math.h>

#define BB 4
#define SS 4096
#define DD 1024
#define HALF (DD/2)
#define TD (3*DD)
#define QKD (2*DD)

// ---------------- scratch (device globals; no allocation allowed) ----------------
__device__ __align__(16) __nv_bfloat16  g_qkbf[(long long)BB*SS*QKD];   // 64MB q,k rows
__device__ __align__(16) __nv_bfloat16  g_P[(long long)BB*SS*SS];       // 128MB unnormalized 3^s
__device__ __align__(16) __nv_bfloat16  g_hbf[(long long)BB*SS*DD];     // 32MB
__device__ __align__(16) unsigned char  g_qf8[(long long)BB*SS*DD];     // 16MB e4m3
__device__ __align__(16) unsigned char  g_kf8[(long long)BB*SS*DD];     // 16MB e4m3
__device__ __align__(16) __nv_bfloat16  g_vwT[(long long)DD*BB*SS];     // 32MB (h@Wvp)^T [d][b*s]
__device__ __align__(16) __nv_bfloat16  g_wqkT[(long long)QKD*DD];      // 4MB  [n][k]
__device__ __align__(16) __nv_bfloat16  g_wprojT[(long long)DD*DD];     // 2MB  [n][k]
__device__ __align__(16) __nv_bfloat16  g_wvbf[(long long)DD*DD];       // 2MB  Wv rows bf16 [in][mid]
__device__ __align__(16) __nv_bfloat16  g_wvpT[(long long)DD*DD];       // 2MB  (Wv@Wproj)^T [out][in]
__device__ float g_bfin[DD];                                            // b_proj + bv@Wproj
__device__ float g_den[(long long)BB*SS];                               // row sums of P
__device__ float g_invf[HALF];
__device__ __align__(8) signed char g_cos[SS*HALF];
__device__ __align__(8) signed char g_sin[SS*HALF];

// ---------------- fast exp2 (single MUFU regardless of fast-math flags) ----------------
__device__ __forceinline__ float ex2f(float x) {
    float r;
    asm("ex2.approx.ftz.f32 %0, %1;" : "=f"(r) : "f"(x));
    return r;
}

// ---------------- ternary rope tables ----------------
__global__ void build_inv_kernel() {
    int j = threadIdx.x;
    float e = (float)j / (float)HALF;
    g_invf[j] = 1.0f / (float)pow(10000.0, (double)e);
}
__global__ void build_tables_kernel() {
    int idx = blockIdx.x * blockDim.x + threadIdx.x;
    if (idx >= SS * HALF) return;
    int s = idx / HALF;
    int j = idx - s * HALF;
    float ang = (float)s * g_invf[j];
    double t = (double)ang;
    double k = rint(t * 0.15915494309189535);
    float r = (float)(t - k * 6.283185307179586);
    float c, sn;
    sincosf(r, &sn, &c);
    g_cos[idx] = (signed char)__float2int_rn(c);
    g_sin[idx] = (signed char)__float2int_rn(sn);
}

// ---------------- zero vwT + wvpT (split-K RED accumulators), on stream B ----------------
#define NZ1 ((long long)DD*BB*SS/8)   // vwT in uint4
#define NZ2 ((long long)DD*DD/8)      // wvpT in uint4
__global__ void prep_zero_kernel(uint4* __restrict__ vw, uint4* __restrict__ wvp) {
    long long i = (long long)blockIdx.x * 256 + threadIdx.x;
    if (i < NZ1) vw[i] = make_uint4(0u, 0u, 0u, 0u);
    else if (i < NZ1 + NZ2) wvp[i - NZ1] = make_uint4(0u, 0u, 0u, 0u);
}

// ---------------- bfinal[j] = b_proj[j] + sum_l b_qkv[2048+l] * w_proj[l][j]  (stream B) ----------------
__global__ void bfin_kernel(const float* __restrict__ b_qkv, const float* __restrict__ w_proj,
                            const float* __restrict__ b_proj) {
    int j = blockIdx.x * 256 + threadIdx.x;
    float acc = b_proj[j];
    for (int l = 0; l < DD; l++) acc += b_qkv[2 * DD + l] * w_proj[(long long)l * DD + j];
    g_bfin[j] = acc;
}

// ---------------- convert Wv slice to bf16 (no transpose): wv[in][mid] ----------------
__global__ __launch_bounds__(256) void cvt_wv_kernel(const float* __restrict__ w_qkv,
                                                     __nv_bfloat16* __restrict__ wv) {
    int idx = blockIdx.x * 256 + threadIdx.x;
    int row = idx >> 8, col4 = (idx & 255) * 4;
    float4 v = *(const float4*)(w_qkv + (long long)row * TD + 2 * DD + col4);
    __nv_bfloat162 o0 = {__float2bfloat16(v.x), __float2bfloat16(v.y)};
    __nv_bfloat162 o1 = {__float2bfloat16(v.z), __float2bfloat16(v.w)};
    __nv_bfloat162* op = (__nv_bfloat162*)(wv + (long long)row * DD + col4);
    op[0] = o0; op[1] = o1;
}

// ---------------- reductions ----------------
__device__ __forceinline__ float block_reduce_sum(float v, float* red) {
    int lane = threadIdx.x & 31, w = threadIdx.x >> 5;
    #pragma unroll
    for (int o = 16; o; o >>= 1) v += __shfl_xor_sync(0xffffffffu, v, o);
    if (lane == 0) red[w] = v;
    __syncthreads();
    if (w == 0) {
        v = (lane < (int)(blockDim.x >> 5)) ? red[lane] : 0.0f;
        #pragma unroll
        for (int o = 16; o; o >>= 1) v += __shfl_xor_sync(0xffffffffu, v, o);
        if (lane == 0) red[0] = v;
    }
    __syncthreads();
    float out = red[0];
    __syncthreads();
    return out;
}

// ---------------- rmsnorm -> bf16, plus out0 = x ----------------
__global__ __launch_bounds__(256) void rmsnorm_kernel(const float* __restrict__ x,
                                                      const float* __restrict__ g,
                                                      __nv_bfloat16* __restrict__ h,
                                                      float* __restrict__ out0) {
    __shared__ float red[32];
    long long base = (long long)blockIdx.x * DD;
    float4 v = *(const float4*)(x + base + (long long)threadIdx.x * 4);
    *(float4*)(out0 + base + (long long)threadIdx.x * 4) = v;

    float ss = v.x*v.x + v.y*v.y + v.z*v.z + v.w*v.w;
    float total = block_reduce_sum(ss, red);
    float r = rsqrtf(total * (1.0f / DD) + 1e-6f);
    float4 gv = *(const float4*)(g + (long long)threadIdx.x * 4);
    __nv_bfloat162 h0 = {__float2bfloat16(v.x*r*gv.x), __float2bfloat16(v.y*r*gv.y)};
    __nv_bfloat162 h1 = {__float2bfloat16(v.z*r*gv.z), __float2bfloat16(v.w*r*gv.w)};
    __nv_bfloat162* hp = (__nv_bfloat162*)(h + base + (long long)threadIdx.x * 4);
    hp[0] = h0; hp[1] = h1;
}

// ---------------- weight transpose + convert f32 -> bf16 ----------------
__global__ __launch_bounds__(256) void transpose_cvt_kernel(
    const float* __restrict__ in, int ldin,
    __nv_bfloat16* __restrict__ out, int ldout)
{
    __shared__ float tile[32][33];
    int r0 = blockIdx.y * 32, c0 = blockIdx.x * 32;
    int tx = threadIdx.x & 31, ty = threadIdx.x >> 5;
    #pragma unroll
    for (int i = 0; i < 4; i++)
        tile[ty + i * 8][tx] = in[(long long)(r0 + ty + i * 8) * ldin + c0 + tx];
    __syncthreads();
    #pragma unroll
    for (int i = 0; i < 4; i++)
        out[(long long)(c0 + ty + i * 8) * ldout + r0 + tx] = __float2bfloat16(tile[tx][ty + i * 8]);
}

// ---------------- rope (vectorized): bf16 qk -> e4m3 q,k ; zeroes den ----------------
__device__ __forceinline__ unsigned short cvt_e4m3x2(float lo, float hi) {
    unsigned short r;
    asm("cvt.rn.satfinite.e4m3x2.f32 %0, %1, %2;" : "=h"(r) : "f"(hi), "f"(lo));
    return r;
}
__global__ __launch_bounds__(256) void rope_kernel(const __nv_bfloat16* __restrict__ qk,
                                                   unsigned char* __restrict__ qo,
                                                   unsigned char* __restrict__ ko,
                                                   float* __restrict__ den) {
    int r = blockIdx.x * 4 + (threadIdx.x >> 6);
    if (threadIdx.x < 4) den[blockIdx.x * 4 + threadIdx.x] = 0.0f;
    int s = r & (SS - 1);
    int j = (threadIdx.x & 63) * 8;

    long long tc8 = *(const long long*)&g_cos[s * HALF + j];
    long long ts8 = *(const long long*)&g_sin[s * HALF + j];
    float cs[8], sn[8];
    #pragma unroll
    for (int i = 0; i < 8; i++) {
        cs[i] = (float)(signed char)(tc8 >> (8 * i));
        sn[i] = (float)(signed char)(ts8 >> (8 * i));
    }

    long long rb = (long long)r * QKD;
    long long ob = (long long)r * DD;
    #pragma unroll
    for (int w = 0; w < 2; w++) {
        const __nv_bfloat16* src = qk + rb + (w ? DD : 0);
        unsigned char* dst = w ? ko : qo;
        uint4 ua = *(const uint4*)(src + j);
        uint4 ub = *(const uint4*)(src + j + HALF);
        float a[8], b[8];
        unsigned va[4] = {ua.x, ua.y, ua.z, ua.w};
        unsigned vb[4] = {ub.x, ub.y, ub.z, ub.w};
        #pragma unroll
        for (int p = 0; p < 4; p++) {
            float2 fa = __bfloat1622float2(*(__nv_bfloat162*)&va[p]);
            float2 fb = __bfloat1622float2(*(__nv_bfloat162*)&vb[p]);
            a[2*p] = fa.x; a[2*p+1] = fa.y;
            b[2*p] = fb.x; b[2*p+1] = fb.y;
        }
        unsigned short lo[4], hi[4];
        #pragma unroll
        for (int p = 0; p < 4; p++) {
            lo[p] = cvt_e4m3x2(a[2*p]*cs[2*p]   - b[2*p]*sn[2*p],
                               a[2*p+1]*cs[2*p+1] - b[2*p+1]*sn[2*p+1]);
            hi[p] = cvt_e4m3x2(b[2*p]*cs[2*p]   + a[2*p]*sn[2*p],
                               b[2*p+1]*cs[2*p+1] + a[2*p+1]*sn[2*p+1]);
        }
        *(uint2*)(dst + ob + j)        = make_uint2((unsigned)lo[0] | ((unsigned)lo[1] << 16),
                                                    (unsigned)lo[2] | ((unsigned)lo[3] << 16));
        *(uint2*)(dst + ob + HALF + j) = make_uint2((unsigned)hi[0] | ((unsigned)hi[1] << 16),
                                                    (unsigned)hi[2] | ((unsigned)hi[3] << 16));
    }
}

// ---------------- mma helpers ----------------
__device__ __forceinline__ void ldsm4(unsigned* r, unsigned addr) {
    asm volatile("ldmatrix.sync.aligned.m8n8.x4.shared.b16 {%0,%1,%2,%3},[%4];"
                 : "=r"(r[0]), "=r"(r[1]), "=r"(r[2]), "=r"(r[3]) : "r"(addr));
}
__device__ __forceinline__ void mma_bf16(float* c, const unsigned* a, unsigned b0, unsigned b1) {
    asm volatile("mma.sync.aligned.m16n8k16.row.col.f32.bf16.bf16.f32 "
                 "{%0,%1,%2,%3},{%4,%5,%6,%7},{%8,%9},{%0,%1,%2,%3};"
                 : "+f"(c[0]), "+f"(c[1]), "+f"(c[2]), "+f"(c[3])
                 : "r"(a[0]), "r"(a[1]), "r"(a[2]), "r"(a[3]), "r"(b0), "r"(b1));
}
__device__ __forceinline__ void mma_e4m3(float* c, const unsigned* a, unsigned b0, unsigned b1) {
    asm volatile("mma.sync.aligned.m16n8k32.row.col.f32.e4m3.e4m3.f32 "
                 "{%0,%1,%2,%3},{%4,%5,%6,%7},{%8,%9},{%0,%1,%2,%3};"
                 : "+f"(c[0]), "+f"(c[1]), "+f"(c[2]), "+f"(c[3])
                 : "r"(a[0]), "r"(a[1]), "r"(a[2]), "r"(a[3]), "r"(b0), "r"(b1));
}
__device__ __forceinline__ void cpasync16(unsigned s, const void* g) {
    asm volatile("cp.async.cg.shared.global [%0], [%1], 16;" :: "r"(s), "l"(g));
}
#define CP_COMMIT() asm volatile("cp.async.commit_group;" ::: "memory")

__device__ __forceinline__ void red_add_f2(float* addr, float a, float b) {
    asm volatile("red.global.add.v2.f32 [%0], {%1, %2};" :: "l"(addr), "f"(a), "f"(b) : "memory");
}
__device__ __forceinline__ void red_add_bf2(__nv_bfloat16* addr, float a, float b) {
    __nv_bfloat162 pv = __floats2bfloat162_rn(a, b);
    unsigned u = *(unsigned*)&pv;
    asm volatile("red.global.add.noftz.bf16x2 [%0], %1;" :: "l"(addr), "r"(u) : "memory");
}

__device__ __forceinline__ unsigned swz(int row, int ch) {
    int o = row * 128 + ch * 16;
    return (unsigned)(o ^ ((o >> 3) & 0x70));
}

// ================= persistent TN GEMM: tile 128x256, 128B k-chunks =================
// EPI: 1 = bf16 out (+bias), 2 = bf16 out = 3^(acc*alpha) + row-sum atomics into dptr,
//      3 = bf16 out plain (SPLITK: RED bf16x2 into pre-zeroed out),
//      4 = RED f32: out += acc/dptr[row] + (hk==0 ? bias : 0)  (out pre-initialized to x)
#define STG 49152u
template <int IN8, int EPI, int SPLITK>
__global__ __launch_bounds__(256) void gemm_tc(
    int T, int gx, int gy, int gz,
    const char* __restrict__ A0, long long ldaB, long long sAB,
    const char* __restrict__ B0, long long ldbB, long long sBB,
    void* __restrict__ Cv, int ldc, long long sC,
    float alpha,
    const float* __restrict__ bias,
    float* __restrict__ dptr, long long sRS)
{
    extern __shared__ __align__(1024) char dsm[];
    unsigned sbase = (unsigned)__cvta_generic_to_shared(dsm);

    const int t = threadIdx.x;
    const int G = gridDim.x;
    const int gxy = gx * gy;
    const int ntL = gxy * gz;
    const int ntP = SPLITK ? ntL * 2 : ntL;
    const int myCount = (ntP - (int)blockIdx.x + G - 1) / G;
    if (myCount <= 0) return;
    const int myTotal = myCount * T;

    const int lrow = t >> 3;
    const int lch  = t & 7;
    const int warp = t >> 5;
    const int wm = warp >> 2;
    const int wn = warp & 3;
    const int lane = t & 31;
    const int lrow16 = lane & 15;
    const int lhalf  = lane >> 4;

    float acc[4][8][4];
    #pragma unroll
    for (int i = 0; i < 4; i++)
        #pragma unroll
        for (int j = 0; j < 8; j++)
            #pragma unroll
            for (int v = 0; v < 4; v++) acc[i][j][v] = 0.0f;

    auto prefetchChunk = [&](int j) {
        if (j < myTotal) {
            int i = j / T, c = j - i * T;
            int p = (int)blockIdx.x + i * G;
            int lt = SPLITK ? (p >> 1) : p;
            int hk = SPLITK ? (p & 1) : 0;
            int z2 = lt / gxy; int rr = lt - z2 * gxy;
            int by = rr / gx, bx = rr - by * gx;
            const char* Ap = A0 + z2 * sAB + (long long)(by * 128) * ldaB;
            const char* Bp = B0 + z2 * sBB + (long long)(bx * 256) * ldbB;
            unsigned aB = sbase + (unsigned)(j % 3) * STG;
            unsigned bB = aB + 16384u;
            long long ko = (long long)c * 128 + lch * 16 + (long long)hk * T * 128;
            #pragma unroll
            for (int ii = 0; ii < 4; ii++)
                cpasync16(aB + swz(lrow + ii * 32, lch), Ap + (long long)(lrow + ii * 32) * ldaB + ko);
            #pragma unroll
            for (int ii = 0; ii < 8; ii++)
                cpasync16(bB + swz(lrow + ii * 32, lch), Bp + (long long)(lrow + ii * 32) * ldbB + ko);
        }
        CP_COMMIT();
    };

    prefetchChunk(0);
    prefetchChunk(1);

    for (int i = 0; i < myCount; i++) {
        for (int c = 0; c < T; c++) {
            int j = i * T + c;
            if (j + 1 < myTotal) {
                asm volatile("cp.async.wait_group 1;" ::: "memory");
            } else {
                asm volatile("cp.async.wait_group 0;" ::: "memory");
            }
            __syncthreads();

            prefetchChunk(j + 2);

            unsigned aB = sbase + (unsigned)(j % 3) * STG;
            unsigned bB = aB + 16384u;

            unsigned afrag[2][4][4], bfrag[2][4][4];
            #pragma unroll
            for (int mi = 0; mi < 4; mi++)
                ldsm4(afrag[0][mi], aB + swz(wm * 64 + mi * 16 + lrow16, lhalf));
            #pragma unroll
            for (int p = 0; p < 4; p++)
                ldsm4(bfrag[0][p], bB + swz(wn * 64 + p * 16 + lrow16, lhalf));

            #pragma unroll
            for (int ks = 0; ks < 4; ks++) {
                int cur = ks & 1, nxt = cur ^ 1;
                if (ks < 3) {
                    #pragma unroll
                    for (int mi = 0; mi < 4; mi++)
                        ldsm4(afrag[nxt][mi], aB + swz(wm * 64 + mi * 16 + lrow16, (ks + 1) * 2 + lhalf));
                    #pragma unroll
                    for (int p = 0; p < 4; p++)
                        ldsm4(bfrag[nxt][p], bB + swz(wn * 64 + p * 16 + lrow16, (ks + 1) * 2 + lhalf));
                }
                #pragma unroll
                for (int mi = 0; mi < 4; mi++) {
                    #pragma unroll
                    for (int ni = 0; ni < 8; ni++) {
                        const unsigned* bf = bfrag[cur][ni >> 1];
                        if (IN8) mma_e4m3(acc[mi][ni], afrag[cur][mi], bf[ni & 1], bf[2 + (ni & 1)]);
                        else     mma_bf16(acc[mi][ni], afrag[cur][mi], bf[ni & 1], bf[2 + (ni & 1)]);
                    }
                }
            }
        }

        // ---------------- epilogue ----------------
        {
            int p = (int)blockIdx.x + i * G;
            int lt = SPLITK ? (p >> 1) : p;
            int hk = SPLITK ? (p & 1) : 0;
            int z = lt / gxy; int rr = lt - z * gxy;
            int by = rr / gx, bx = rr - by * gx;
            int m0 = by * 128, n0 = bx * 256;
            const int g = lane >> 2, tig = lane & 3;
            #pragma unroll
            for (int mi = 0; mi < 4; mi++) {
                #pragma unroll
                for (int half = 0; half < 2; half++) {
                    int row = m0 + wm * 64 + mi * 16 + g + half * 8;
                    float rs = 0.0f;
                    if (EPI == 4) rs = 1.0f / dptr[z * sRS + row];
                    float rsum = 0.0f;
                    #pragma unroll
                    for (int ni = 0; ni < 8; ni++) {
                        int col = n0 + wn * 64 + ni * 8 + tig * 2;
                        float v0 = acc[mi][ni][half * 2];
                        float v1 = acc[mi][ni][half * 2 + 1];
                        if (EPI == 1) {
                            v0 += bias[col]; v1 += bias[col + 1];
                            __nv_bfloat16* C = (__nv_bfloat16*)Cv + z * sC;
                            __nv_bfloat162 pv = {__float2bfloat16(v0), __float2bfloat16(v1)};
                            *(__nv_bfloat162*)(C + (long long)row * ldc + col) = pv;
                        } else if (EPI == 2) {
                            v0 = ex2f(v0 * alpha); v1 = ex2f(v1 * alpha); rsum += v0 + v1;
                            __nv_bfloat16* C = (__nv_bfloat16*)Cv + z * sC;
                            __nv_bfloat162 pv = {__float2bfloat16(v0), __float2bfloat16(v1)};
                            *(__nv_bfloat162*)(C + (long long)row * ldc + col) = pv;
                        } else if (EPI == 3) {
                            __nv_bfloat16* C = (__nv_bfloat16*)Cv + z * sC;
                            if (SPLITK) {
                                red_add_bf2(C + (long long)row * ldc + col, v0, v1);
                            } else {
                                __nv_bfloat162 pv = {__float2bfloat16(v0), __float2bfloat16(v1)};
                                *(__nv_bfloat162*)(C + (long long)row * ldc + col) = pv;
                            }
                        } else {   // EPI == 4: RED accumulate + one-shot bias on hk==0
                            float b0 = 0.0f, b1 = 0.0f;
                            if (hk == 0) { b0 = bias[col]; b1 = bias[col + 1]; }
                            float* C = (float*)Cv + z * sC;
                            red_add_f2(C + (long long)row * ldc + col, v0 * rs + b0, v1 * rs + b1);
                        }
                    }
                    if (EPI == 2) {
                        rsum += __shfl_xor_sync(0xffffffffu, rsum, 1);
                        rsum += __shfl_xor_sync(0xffffffffu, rsum, 2);
                        if (tig == 0) atomicAdd(dptr + z * sRS + row, rsum);
                    }
                }
            }
        }
        #pragma unroll
        for (int a = 0; a < 4; a++)
            #pragma unroll
            for (int b = 0; b < 8; b++)
                #pragma unroll
                for (int v = 0; v < 4; v++) acc[a][b][v] = 0.0f;
    }
}

// ---------------- launch ----------------
extern "C" void kernel_launch(void* const* d_in, const int* in_sizes, int n_in,
                              void* d_out, int out_size) {
    const float* x      = (const float*)d_in[0];
    const float* g_norm = (const float*)d_in[1];
    const float* w_qkv  = (const float*)d_in[2];
    const float* b_qkv  = (const float*)d_in[3];
    const float* w_proj = (const float*)d_in[4];
    const float* b_proj = (const float*)d_in[5];
    float* out = (float*)d_out;

    void *pqk, *pP, *ph, *pq, *pk, *pvw, *pwq, *pwp, *pwv, *pwvp, *pd, *pbf;
    cudaGetSymbolAddress(&pqk, g_qkbf);
    cudaGetSymbolAddress(&pP, g_P);
    cudaGetSymbolAddress(&ph, g_hbf);
    cudaGetSymbolAddress(&pq, g_qf8);
    cudaGetSymbolAddress(&pk, g_kf8);
    cudaGetSymbolAddress(&pvw, g_vwT);
    cudaGetSymbolAddress(&pwq, g_wqkT);
    cudaGetSymbolAddress(&pwp, g_wprojT);
    cudaGetSymbolAddress(&pwv, g_wvbf);
    cudaGetSymbolAddress(&pwvp, g_wvpT);
    cudaGetSymbolAddress(&pd, g_den);
    cudaGetSymbolAddress(&pbf, g_bfin);
    __nv_bfloat16* qkbf  = (__nv_bfloat16*)pqk;
    __nv_bfloat16* P     = (__nv_bfloat16*)pP;
    __nv_bfloat16* hbf   = (__nv_bfloat16*)ph;
    unsigned char* qf8   = (unsigned char*)pq;
    unsigned char* kf8   = (unsigned char*)pk;
    __nv_bfloat16* vwT   = (__nv_bfloat16*)pvw;
    __nv_bfloat16* wqkT  = (__nv_bfloat16*)pwq;
    __nv_bfloat16* wprojT= (__nv_bfloat16*)pwp;
    __nv_bfloat16* wvbf  = (__nv_bfloat16*)pwv;
    __nv_bfloat16* wvpT  = (__nv_bfloat16*)pwvp;
    float* den           = (float*)pd;
    float* bfin          = (float*)pbf;

    int sm = 148;
    cudaDeviceGetAttribute(&sm, cudaDevAttrMultiProcessorCount, 0);

    const int SMEM = 3 * (int)STG;   // 144KB
    cudaFuncSetAttribute(gemm_tc<0,1,0>, cudaFuncAttributeMaxDynamicSharedMemorySize, SMEM);
    cudaFuncSetAttribute(gemm_tc<0,3,1>, cudaFuncAttributeMaxDynamicSharedMemorySize, SMEM);
    cudaFuncSetAttribute(gemm_tc<1,2,0>, cudaFuncAttributeMaxDynamicSharedMemorySize, SMEM);
    cudaFuncSetAttribute(gemm_tc<0,4,1>, cudaFuncAttributeMaxDynamicSharedMemorySize, SMEM);

    // one-time stream/event creation (first call is the uncaptured correctness run)
    static cudaStream_t sB = nullptr;
    static cudaEvent_t evFork, evWqk, evTab, evH, evVW;
    if (!sB) {
        cudaStreamCreateWithFlags(&sB, cudaStreamNonBlocking);
        cudaEventCreateWithFlags(&evFork, cudaEventDisableTiming);
        cudaEventCreateWithFlags(&evWqk, cudaEventDisableTiming);
        cudaEventCreateWithFlags(&evTab, cudaEventDisableTiming);
        cudaEventCreateWithFlags(&evH, cudaEventDisableTiming);
        cudaEventCreateWithFlags(&evVW, cudaEventDisableTiming);
    }

    // ---- fork stream B off the main (capturing) stream ----
    cudaEventRecord(evFork, 0);
    cudaStreamWaitEvent(sB, evFork, 0);

    // ---- stream B: wqk transpose (gate for QK GEMM), tables, prep, bfinal, wvp GEMM ----
    transpose_cvt_kernel<<<dim3(QKD / 32, DD / 32), 256, 0, sB>>>(w_qkv, TD, wqkT, DD);
    cudaEventRecord(evWqk, sB);
    build_inv_kernel<<<1, HALF, 0, sB>>>();
    build_tables_kernel<<<(SS * HALF + 255) / 256, 256, 0, sB>>>();
    cudaEventRecord(evTab, sB);
    cvt_wv_kernel<<<DD * DD / 1024, 256, 0, sB>>>(w_qkv, wvbf);
    transpose_cvt_kernel<<<dim3(DD / 32, DD / 32), 256, 0, sB>>>(w_proj, DD, wprojT, DD);
    prep_zero_kernel<<<(int)((NZ1 + NZ2 + 255) / 256), 256, 0, sB>>>((uint4*)vwT, (uint4*)wvpT);
    bfin_kernel<<<DD / 256, 256, 0, sB>>>(b_qkv, w_proj, b_proj);
    {   // wvpT = (Wv@Wproj)^T  (M=1024,N=1024,K=1024; split-K=2 RED bf16x2)
        int gx = DD / 256, gy = DD / 128, gz = 1;
        int ntP = 2 * gx * gy * gz, G = ntP < sm ? ntP : sm;
        gemm_tc<0,3,1><<<G, 256, SMEM, sB>>>(
            DD * 2 / 128 / 2, gx, gy, gz,
            (const char*)wprojT, DD * 2, 0LL,
            (const char*)wvbf, DD * 2, 0LL,
            wvpT, DD, 0LL,
            1.0f, nullptr, nullptr, 0LL);
    }

    // ---- stream A (main): rmsnorm (+ out=x init) -> QK GEMM ----
    rmsnorm_kernel<<<BB * SS, 256>>>(x, g_norm, hbf, out);
    cudaEventRecord(evH, 0);
    cudaStreamWaitEvent(0, evWqk, 0);
    {   // qk = h @ w_qk + b_qk -> bf16  (M=16384, N=2048, K=1024)
        int gx = QKD / 256, gy = (BB * SS) / 128, gz = 1;
        int nt = gx * gy * gz, G = nt < sm ? nt : sm;
        gemm_tc<0,1,0><<<G, 256, SMEM>>>(
            DD * 2 / 128, gx, gy, gz,
            (const char*)hbf, DD * 2, 0LL,
            (const char*)wqkT, DD * 2, 0LL,
            qkbf, QKD, 0LL,
            1.0f, b_qkv, nullptr, 0LL);
    }

    // ---- stream B: vw GEMM once h is ready ----
    cudaStreamWaitEvent(sB, evH, 0);
    {   // vwT[d][b*s] += wvpT @ h^T  (M=1024, N=16384, K=1024; split-K=2 RED bf16x2)
        int gx = (BB * SS) / 256, gy = DD / 128, gz = 1;
        int ntP = 2 * gx * gy * gz, G = ntP < sm ? ntP : sm;
        gemm_tc<0,3,1><<<G, 256, SMEM, sB>>>(
            DD * 2 / 128 / 2, gx, gy, gz,
            (const char*)wvpT, DD * 2, 0LL,
            (const char*)hbf, DD * 2, 0LL,
            vwT, BB * SS, 0LL,
            1.0f, nullptr, nullptr, 0LL);
    }
    cudaEventRecord(evVW, sB);

    // ---- stream A: rope (needs tables) -> P GEMM ----
    cudaStreamWaitEvent(0, evTab, 0);
    rope_kernel<<<BB * SS / 4, 256>>>(qkbf, qf8, kf8, den);
    {   // P = 3^(q@k^T / 32) -> bf16, fused row-sum atomics into den  (M=N=4096, K=1024 fp8)
        int gx = SS / 256, gy = SS / 128, gz = BB;
        int nt = gx * gy * gz, G = nt < sm ? nt : sm;
        gemm_tc<1,2,0><<<G, 256, SMEM>>>(
            DD / 128, gx, gy, gz,
            (const char*)qf8, DD, (long long)SS * DD,
            (const char*)kf8, DD, (long long)SS * DD,
            P, SS, (long long)SS * SS,
            1.5849625007211562f / 32.0f, nullptr, den, (long long)SS);
    }

    // ---- join B, then final GEMM on A ----
    cudaStreamWaitEvent(0, evVW, 0);
    {   // out += (P @ vwT^T)/den + bfinal (hk0 only)   (split-K=2 RED f32; out pre-initialized to x)
        int gx = DD / 256, gy = SS / 128, gz = BB;
        int ntP = 2 * gx * gy * gz, G = ntP < sm ? ntP : sm;
        gemm_tc<0,4,1><<<G, 256, SMEM>>>(
            SS * 2 / 128 / 2, gx, gy, gz,
            (const char*)P, (long long)SS * 2, (long long)SS * SS * 2,
            (const char*)vwT, (long long)BB * SS * 2, (long long)SS * 2,
            out, DD, (long long)SS * DD,
            1.0f, bfin, den, (long long)SS);
    }
}